// round 2
// baseline (speedup 1.0000x reference)
#include <cuda_runtime.h>
#include <math.h>

#define NB 128
#define ND 64
#define NL0 4096
#define NL1 2048
#define NL2 1024
#define NL3 512

// Scratch (static device allocations are allowed; cudaMalloc is not)
__device__ float g_pe[NL0 * ND];                      // 1 MB positional table
__device__ float g_wt[3][256][ND];                    // reorganized conv weights [stage][k*64+ci][co]
__device__ float g_emb[(size_t)NB * NL0 * ND];        // 134 MB
__device__ float g_h1[(size_t)NB * NL1 * ND];         // 67 MB
__device__ float g_h2[(size_t)NB * NL2 * ND];         // 33.5 MB

// ---------------------------------------------------------------------------
// Positional embedding table, computed in double to match the reference's
// fp32 rounding chain: div = fp32(exp(arg_fp32)), ang = fp32(l * div), sin/cos
// of that exact rounded angle evaluated in double (so arg-reduction error of
// sinf on large args never appears).
// ---------------------------------------------------------------------------
__global__ void pe_kernel() {
    int idx = blockIdx.x * blockDim.x + threadIdx.x;
    if (idx >= NL0 * 32) return;
    int l = idx >> 5, i = idx & 31;
    float argf = (float)(2 * i) * (float)(-log(10000.0) / 64.0);
    float divf = (float)exp((double)argf);
    float angf = (float)l * divf;
    double ang = (double)angf;
    g_pe[l * ND + 2 * i]     = (float)sin(ang);
    g_pe[l * ND + 2 * i + 1] = (float)cos(ang);
}

// ---------------------------------------------------------------------------
// Reorganize c_w{s} (co, ci, k) -> g_wt[s][k*64+ci][co] so the stage kernel
// can read weight columns as float4 (4 consecutive out-channels).
// ---------------------------------------------------------------------------
__global__ void wt_kernel(const float* __restrict__ w1,
                          const float* __restrict__ w2,
                          const float* __restrict__ w3) {
    int idx = blockIdx.x * blockDim.x + threadIdx.x;
    if (idx >= 3 * 64 * 64 * 4) return;
    int s = idx / 16384;
    int rem = idx - s * 16384;          // rem = co*256 + ci*4 + kk
    int co = rem >> 8;
    int ci = (rem >> 2) & 63;
    int kk = rem & 3;
    const float* w = (s == 0) ? w1 : (s == 1) ? w2 : w3;
    g_wt[s][kk * 64 + ci][co] = w[rem];
}

// ---------------------------------------------------------------------------
// Token embedding: channel c -> kernel group g=c%4 (sizes 3/5/7/9, pad g+1),
// within-group filter j=c/4. Output layout (B, L, D), plus PE.
// ---------------------------------------------------------------------------
__global__ void emb_kernel(const float* __restrict__ x,
                           const float* __restrict__ w3, const float* __restrict__ b3,
                           const float* __restrict__ w5, const float* __restrict__ b5,
                           const float* __restrict__ w7, const float* __restrict__ b7,
                           const float* __restrict__ w9, const float* __restrict__ b9) {
    __shared__ float xs[272];
    __shared__ float wsm[384];
    __shared__ float bsm[64];
    int tid = threadIdx.x;
    int b  = blockIdx.y;
    int l0 = blockIdx.x * 256;

    if (tid < 48)  wsm[tid]        = w3[tid];
    if (tid < 80)  wsm[48  + tid]  = w5[tid];
    if (tid < 112) wsm[128 + tid]  = w7[tid];
    if (tid < 144) wsm[240 + tid]  = w9[tid];
    if (tid < 64) {
        int g = tid & 3, j = tid >> 2;
        bsm[tid] = (g == 0 ? b3 : g == 1 ? b5 : g == 2 ? b7 : b9)[j];
    }
    const float* xb = x + (size_t)b * NL0;
    for (int i = tid; i < 272; i += 256) {
        int gl = l0 - 4 + i;
        xs[i] = (gl >= 0 && gl < NL0) ? xb[gl] : 0.f;
    }
    __syncthreads();

    int c = tid & 63;
    int g = c & 3, j = c >> 2;
    int ks  = 3 + 2 * g;
    int pad = g + 1;
    int woff = (g == 0 ? 0 : g == 1 ? 48 : g == 2 ? 128 : 240) + j * ks;
    float wreg[9];
#pragma unroll
    for (int k = 0; k < 9; ++k) wreg[k] = (k < ks) ? wsm[woff + k] : 0.f;
    float bias = bsm[c];

    float* ob        = g_emb + ((size_t)b * NL0 + l0) * ND + c;
    const float* peb = g_pe + (size_t)l0 * ND + c;

    for (int p = (tid >> 6); p < 256; p += 4) {
        float acc = bias;
        int base = 4 + p - pad;
#pragma unroll
        for (int k = 0; k < 9; ++k) acc = fmaf(wreg[k], xs[base + k], acc);
        ob[p * ND] = acc + peb[p * ND];
    }
}

// ---------------------------------------------------------------------------
// One compression stage: conv1d(64->64, k=4, s=2, p=1) -> tanh [-> LN over D].
// Persistent CTAs. Per tile: 64 output positions x 64 channels.
// Smem: Xs[130][65] input halo (stride 65 => bank-conflict-free), Ws 256x64.
// Thread micro-tile: 4 positions x 4 channels -> 16 FMA per 32 smem bytes.
// ---------------------------------------------------------------------------
template <bool HAS_LN>
__global__ void stage_kernel(const float* __restrict__ in, float* __restrict__ out,
                             const float* __restrict__ wt, const float* __restrict__ bias,
                             const float* __restrict__ lng, const float* __restrict__ lnb,
                             int Lin, int Lout, int numTiles) {
    extern __shared__ float smem[];
    float*  Xs   = smem;                         // 130*65 = 8450 (+2 pad) floats
    float4* Ws4  = (float4*)(smem + 8452);       // 4096 float4 (16B aligned)
    float*  bsm  = smem + 8452 + 16384;
    float*  gsm  = bsm + 64;
    float*  lbsm = bsm + 128;

    int tid = threadIdx.x;
    const float4* wt4 = (const float4*)wt;
    for (int i = tid; i < 4096; i += 256) Ws4[i] = wt4[i];
    if (tid < 64) {
        bsm[tid] = bias[tid];
        if (HAS_LN) { gsm[tid] = lng[tid]; lbsm[tid] = lnb[tid]; }
    }

    int tx = tid & 15, ty = tid >> 4;
    int co0 = tx * 4, p0 = ty * 4;
    int tilesPerB = Lout >> 6;

    for (int tile = blockIdx.x; tile < numTiles; tile += gridDim.x) {
        int b = tile / tilesPerB;
        int t = tile - b * tilesPerB;
        int l0 = t << 6;
        int g0 = 2 * l0 - 1;

        __syncthreads();   // protect Xs against previous iteration's readers
        const float* inb = in + (size_t)b * Lin * ND;
        for (int i = tid; i < 130 * 64; i += 256) {
            int row = i >> 6, cc = i & 63;
            int gg = g0 + row;
            Xs[row * 65 + cc] = (gg >= 0 && gg < Lin) ? inb[(size_t)gg * 64 + cc] : 0.f;
        }
        __syncthreads();

        float acc[4][4];
#pragma unroll
        for (int p = 0; p < 4; ++p)
#pragma unroll
            for (int i = 0; i < 4; ++i) acc[p][i] = 0.f;

#pragma unroll
        for (int kk = 0; kk < 4; ++kk) {
            const float*  xr = Xs + (2 * p0 + kk) * 65;
            const float4* wr = Ws4 + (kk * 64) * 16 + tx;
#pragma unroll 8
            for (int ci = 0; ci < 64; ++ci) {
                float4 w = wr[ci * 16];
                float x0 = xr[ci];
                float x1 = xr[130 + ci];
                float x2 = xr[260 + ci];
                float x3 = xr[390 + ci];
                acc[0][0] = fmaf(x0, w.x, acc[0][0]);
                acc[0][1] = fmaf(x0, w.y, acc[0][1]);
                acc[0][2] = fmaf(x0, w.z, acc[0][2]);
                acc[0][3] = fmaf(x0, w.w, acc[0][3]);
                acc[1][0] = fmaf(x1, w.x, acc[1][0]);
                acc[1][1] = fmaf(x1, w.y, acc[1][1]);
                acc[1][2] = fmaf(x1, w.z, acc[1][2]);
                acc[1][3] = fmaf(x1, w.w, acc[1][3]);
                acc[2][0] = fmaf(x2, w.x, acc[2][0]);
                acc[2][1] = fmaf(x2, w.y, acc[2][1]);
                acc[2][2] = fmaf(x2, w.z, acc[2][2]);
                acc[2][3] = fmaf(x2, w.w, acc[2][3]);
                acc[3][0] = fmaf(x3, w.x, acc[3][0]);
                acc[3][1] = fmaf(x3, w.y, acc[3][1]);
                acc[3][2] = fmaf(x3, w.z, acc[3][2]);
                acc[3][3] = fmaf(x3, w.w, acc[3][3]);
            }
        }

        float* outb = out + ((size_t)b * Lout + l0) * ND;
#pragma unroll
        for (int p = 0; p < 4; ++p) {
            float t0 = tanhf(acc[p][0] + bsm[co0 + 0]);
            float t1 = tanhf(acc[p][1] + bsm[co0 + 1]);
            float t2 = tanhf(acc[p][2] + bsm[co0 + 2]);
            float t3 = tanhf(acc[p][3] + bsm[co0 + 3]);
            float4 o4;
            if (HAS_LN) {
                float s1 = t0 + t1 + t2 + t3;
                float s2 = t0 * t0 + t1 * t1 + t2 * t2 + t3 * t3;
#pragma unroll
                for (int o = 1; o < 16; o <<= 1) {
                    s1 += __shfl_xor_sync(0xffffffffu, s1, o);
                    s2 += __shfl_xor_sync(0xffffffffu, s2, o);
                }
                float m   = s1 * (1.f / 64.f);
                float v   = s2 * (1.f / 64.f) - m * m;
                float inv = 1.f / sqrtf(v + 1e-5f);
                o4.x = (t0 - m) * inv * gsm[co0 + 0] + lbsm[co0 + 0];
                o4.y = (t1 - m) * inv * gsm[co0 + 1] + lbsm[co0 + 1];
                o4.z = (t2 - m) * inv * gsm[co0 + 2] + lbsm[co0 + 2];
                o4.w = (t3 - m) * inv * gsm[co0 + 3] + lbsm[co0 + 3];
            } else {
                o4.x = t0; o4.y = t1; o4.z = t2; o4.w = t3;
            }
            *(float4*)(outb + (size_t)(p0 + p) * ND + co0) = o4;
        }
    }
}

extern "C" void kernel_launch(void* const* d_in, const int* in_sizes, int n_in,
                              void* d_out, int out_size) {
    const float* x   = (const float*)d_in[0];
    const float* tw3 = (const float*)d_in[1];
    const float* tb3 = (const float*)d_in[2];
    const float* tw5 = (const float*)d_in[3];
    const float* tb5 = (const float*)d_in[4];
    const float* tw7 = (const float*)d_in[5];
    const float* tb7 = (const float*)d_in[6];
    const float* tw9 = (const float*)d_in[7];
    const float* tb9 = (const float*)d_in[8];
    const float* cw1 = (const float*)d_in[9];
    const float* cb1 = (const float*)d_in[10];
    const float* cw2 = (const float*)d_in[11];
    const float* cb2 = (const float*)d_in[12];
    const float* cw3 = (const float*)d_in[13];
    const float* cb3 = (const float*)d_in[14];
    const float* lg1 = (const float*)d_in[15];
    const float* lb1 = (const float*)d_in[16];
    const float* lg2 = (const float*)d_in[17];
    const float* lb2 = (const float*)d_in[18];
    (void)in_sizes; (void)n_in; (void)out_size;

    void *pe_p, *wt_p, *emb_p, *h1_p, *h2_p;
    cudaGetSymbolAddress(&pe_p,  g_pe);
    cudaGetSymbolAddress(&wt_p,  g_wt);
    cudaGetSymbolAddress(&emb_p, g_emb);
    cudaGetSymbolAddress(&h1_p,  g_h1);
    cudaGetSymbolAddress(&h2_p,  g_h2);
    float* emb = (float*)emb_p;
    float* h1  = (float*)h1_p;
    float* h2  = (float*)h2_p;
    float* wtb = (float*)wt_p;
    (void)pe_p;

    const int smemsz = (8452 + 16384 + 192) * 4;   // 100,112 B -> 2 CTAs/SM
    cudaFuncSetAttribute((const void*)stage_kernel<true>,
                         cudaFuncAttributeMaxDynamicSharedMemorySize, smemsz);
    cudaFuncSetAttribute((const void*)stage_kernel<false>,
                         cudaFuncAttributeMaxDynamicSharedMemorySize, smemsz);

    pe_kernel<<<(NL0 * 32 + 255) / 256, 256>>>();
    wt_kernel<<<(3 * 64 * 64 * 4 + 255) / 256, 256>>>(cw1, cw2, cw3);

    dim3 eg(NL0 / 256, NB);
    emb_kernel<<<eg, 256>>>(x, tw3, tb3, tw5, tb5, tw7, tb7, tw9, tb9);

    stage_kernel<true ><<<296, 256, smemsz>>>(emb, h1, wtb + 0 * 256 * 64, cb1, lg1, lb1,
                                              NL0, NL1, NB * (NL1 / 64));
    stage_kernel<true ><<<296, 256, smemsz>>>(h1, h2, wtb + 1 * 256 * 64, cb2, lg2, lb2,
                                              NL1, NL2, NB * (NL2 / 64));
    stage_kernel<false><<<296, 256, smemsz>>>(h2, (float*)d_out, wtb + 2 * 256 * 64, cb3,
                                              nullptr, nullptr, NL2, NL3, NB * (NL3 / 64));
}

// round 3
// speedup vs baseline: 1.1504x; 1.1504x over previous
#include <cuda_runtime.h>
#include <math.h>

#define NB 128
#define ND 64
#define NL0 4096
#define NL1 2048
#define NL2 1024
#define NL3 512

typedef unsigned long long u64;

// Scratch (static device allocations are allowed; cudaMalloc is not)
__device__ float g_pe[NL0 * ND];                      // 1 MB positional table
__device__ float g_wt[3][128][128];                   // repacked conv weights [stage][kk*32+ci/2][lane-major co/ci-parity]
__device__ float g_emb[(size_t)NB * NL0 * ND];        // 134 MB
__device__ float g_h1[(size_t)NB * NL1 * ND];         // 67 MB
__device__ float g_h2[(size_t)NB * NL2 * ND];         // 33.5 MB

__device__ __forceinline__ void ffma2(u64& d, u64 a, u64 b) {
    asm("fma.rn.f32x2 %0, %1, %2, %0;" : "+l"(d) : "l"(a), "l"(b));
}
__device__ __forceinline__ float unpack_sum(u64 v) {
    float lo, hi;
    asm("mov.b64 {%0,%1}, %2;" : "=f"(lo), "=f"(hi) : "l"(v));
    return lo + hi;
}

// ---------------------------------------------------------------------------
// Positional embedding table (double precision to match reference's fp32
// rounding chain exactly; avoids sinf large-arg reduction error).
// ---------------------------------------------------------------------------
__global__ void pe_kernel() {
    int idx = blockIdx.x * blockDim.x + threadIdx.x;
    if (idx >= NL0 * 32) return;
    int l = idx >> 5, i = idx & 31;
    float argf = (float)(2 * i) * (float)(-log(10000.0) / 64.0);
    float divf = (float)exp((double)argf);
    float angf = (float)l * divf;
    double ang = (double)angf;
    g_pe[l * ND + 2 * i]     = (float)sin(ang);
    g_pe[l * ND + 2 * i + 1] = (float)cos(ang);
}

// ---------------------------------------------------------------------------
// Repack c_w{s} (co, ci, kk) into the conflict-free f32x2 layout:
//   row = kk*32 + ci/2   (128 floats per row)
//   col = ((co&3)>>1)*64 + (co>>2)*4 + (co&1)*2 + (ci&1)
// so lane tx's 4 co-channels x 1 ci-pair form two contiguous 16B chunks at
// tx*16B within each 64-float half — LDS.128, conflict-free, pairs (ci-even,
// ci-odd) adjacent for FFMA2.
// ---------------------------------------------------------------------------
__global__ void wt_kernel(const float* __restrict__ w1,
                          const float* __restrict__ w2,
                          const float* __restrict__ w3) {
    int idx = blockIdx.x * blockDim.x + threadIdx.x;
    if (idx >= 3 * 64 * 64 * 4) return;
    int s = idx / 16384;
    int rem = idx - s * 16384;          // rem = co*256 + ci*4 + kk
    int co = rem >> 8;
    int ci = (rem >> 2) & 63;
    int kk = rem & 3;
    const float* w = (s == 0) ? w1 : (s == 1) ? w2 : w3;
    int row = kk * 32 + (ci >> 1);
    int col = ((co & 3) >> 1) * 64 + (co >> 2) * 4 + (co & 1) * 2 + (ci & 1);
    g_wt[s][row][col] = w[rem];
}

// ---------------------------------------------------------------------------
// Token embedding: channel c -> kernel group g=c%4 (sizes 3/5/7/9, pad g+1),
// within-group filter j=c/4. Output layout (B, L, D), plus PE.
// ---------------------------------------------------------------------------
__global__ void emb_kernel(const float* __restrict__ x,
                           const float* __restrict__ w3, const float* __restrict__ b3,
                           const float* __restrict__ w5, const float* __restrict__ b5,
                           const float* __restrict__ w7, const float* __restrict__ b7,
                           const float* __restrict__ w9, const float* __restrict__ b9) {
    __shared__ float xs[272];
    __shared__ float wsm[384];
    __shared__ float bsm[64];
    int tid = threadIdx.x;
    int b  = blockIdx.y;
    int l0 = blockIdx.x * 256;

    if (tid < 48)  wsm[tid]        = w3[tid];
    if (tid < 80)  wsm[48  + tid]  = w5[tid];
    if (tid < 112) wsm[128 + tid]  = w7[tid];
    if (tid < 144) wsm[240 + tid]  = w9[tid];
    if (tid < 64) {
        int g = tid & 3, j = tid >> 2;
        bsm[tid] = (g == 0 ? b3 : g == 1 ? b5 : g == 2 ? b7 : b9)[j];
    }
    const float* xb = x + (size_t)b * NL0;
    for (int i = tid; i < 272; i += 256) {
        int gl = l0 - 4 + i;
        xs[i] = (gl >= 0 && gl < NL0) ? xb[gl] : 0.f;
    }
    __syncthreads();

    int c = tid & 63;
    int g = c & 3, j = c >> 2;
    int ks  = 3 + 2 * g;
    int pad = g + 1;
    int woff = (g == 0 ? 0 : g == 1 ? 48 : g == 2 ? 128 : 240) + j * ks;
    float wreg[9];
#pragma unroll
    for (int k = 0; k < 9; ++k) wreg[k] = (k < ks) ? wsm[woff + k] : 0.f;
    float bias = bsm[c];

    float* ob        = g_emb + ((size_t)b * NL0 + l0) * ND + c;
    const float* peb = g_pe + (size_t)l0 * ND + c;

    for (int p = (tid >> 6); p < 256; p += 4) {
        float acc = bias;
        int base = 4 + p - pad;
#pragma unroll
        for (int k = 0; k < 9; ++k) acc = fmaf(wreg[k], xs[base + k], acc);
        ob[p * ND] = acc + peb[p * ND];
    }
}

// ---------------------------------------------------------------------------
// One compression stage: conv1d(64->64, k=4, s=2, p=1) -> tanh [-> LN over D].
// Persistent CTAs; tile = 64 out positions x 64 channels.
// Inner loop per (kk, ci-quad): 4 w-LDS.128 + 4 x-LDS.128 + 32 FFMA2
// (fma.rn.f32x2 packed over the ci reduction dim: lo=even-ci, hi=odd-ci).
// Xs stride 68 floats (16B aligned rows, broadcast x loads). Weight smem layout
// is lane-contiguous (see wt_kernel) -> conflict-free LDS.128.
// ---------------------------------------------------------------------------
template <bool HAS_LN>
__global__ void __launch_bounds__(256, 2)
stage_kernel(const float* __restrict__ in, float* __restrict__ out,
             const float* __restrict__ wt, const float* __restrict__ bias,
             const float* __restrict__ lng, const float* __restrict__ lnb,
             int Lin, int Lout, int numTiles) {
    extern __shared__ float smem[];
    float* Xs   = smem;                       // 130*68 = 8840 floats
    float* Ws   = smem + 8840;                // 16384 floats (128x128)
    float* bsm  = smem + 8840 + 16384;
    float* gsm  = bsm + 64;
    float* lbsm = bsm + 128;

    int tid = threadIdx.x;
    const float4* wt4 = (const float4*)wt;
    float4* Ws4c = (float4*)Ws;
    for (int i = tid; i < 4096; i += 256) Ws4c[i] = wt4[i];
    if (tid < 64) {
        bsm[tid] = bias[tid];
        if (HAS_LN) { gsm[tid] = lng[tid]; lbsm[tid] = lnb[tid]; }
    }

    int tx = tid & 15, ty = tid >> 4;
    int co0 = tx * 4, p0 = ty * 4;
    int tilesPerB = Lout >> 6;

    for (int tile = blockIdx.x; tile < numTiles; tile += gridDim.x) {
        int b = tile / tilesPerB;
        int t = tile - b * tilesPerB;
        int l0 = t << 6;
        int g0 = 2 * l0 - 1;

        __syncthreads();   // protect Xs against previous iteration's readers
        const float* inb = in + (size_t)b * Lin * ND;
        for (int i = tid; i < 130 * 64; i += 256) {
            int row = i >> 6, cc = i & 63;
            int gg = g0 + row;
            Xs[row * 68 + cc] = (gg >= 0 && gg < Lin) ? inb[(size_t)gg * 64 + cc] : 0.f;
        }
        __syncthreads();

        u64 acc[4][4];
#pragma unroll
        for (int p = 0; p < 4; ++p)
#pragma unroll
            for (int i = 0; i < 4; ++i) acc[p][i] = 0ull;

#pragma unroll 1
        for (int kk = 0; kk < 4; ++kk) {
            const float* xk = Xs + (2 * p0 + kk) * 68;
            const ulonglong2* wk = (const ulonglong2*)(Ws + kk * 32 * 128) + tx;
#pragma unroll 4
            for (int cq = 0; cq < 16; ++cq) {
                const ulonglong2* wp = wk + cq * 64;   // 2 rows of 32 ulonglong2
                ulonglong2 wA0 = wp[0];    // ci-pair A: co0,co1
                ulonglong2 wA1 = wp[16];   // ci-pair A: co2,co3
                ulonglong2 wB0 = wp[32];   // ci-pair B: co0,co1
                ulonglong2 wB1 = wp[48];   // ci-pair B: co2,co3
                const float* xq = xk + cq * 4;
#pragma unroll
                for (int p = 0; p < 4; ++p) {
                    ulonglong2 xv = *(const ulonglong2*)(xq + p * 136);
                    ffma2(acc[p][0], xv.x, wA0.x);
                    ffma2(acc[p][1], xv.x, wA0.y);
                    ffma2(acc[p][2], xv.x, wA1.x);
                    ffma2(acc[p][3], xv.x, wA1.y);
                    ffma2(acc[p][0], xv.y, wB0.x);
                    ffma2(acc[p][1], xv.y, wB0.y);
                    ffma2(acc[p][2], xv.y, wB1.x);
                    ffma2(acc[p][3], xv.y, wB1.y);
                }
            }
        }

        float* outb = out + ((size_t)b * Lout + l0) * ND;
#pragma unroll
        for (int p = 0; p < 4; ++p) {
            float t0 = tanhf(unpack_sum(acc[p][0]) + bsm[co0 + 0]);
            float t1 = tanhf(unpack_sum(acc[p][1]) + bsm[co0 + 1]);
            float t2 = tanhf(unpack_sum(acc[p][2]) + bsm[co0 + 2]);
            float t3 = tanhf(unpack_sum(acc[p][3]) + bsm[co0 + 3]);
            float4 o4;
            if (HAS_LN) {
                float s1 = t0 + t1 + t2 + t3;
                float s2 = t0 * t0 + t1 * t1 + t2 * t2 + t3 * t3;
#pragma unroll
                for (int o = 1; o < 16; o <<= 1) {
                    s1 += __shfl_xor_sync(0xffffffffu, s1, o);
                    s2 += __shfl_xor_sync(0xffffffffu, s2, o);
                }
                float m   = s1 * (1.f / 64.f);
                float v   = s2 * (1.f / 64.f) - m * m;
                float inv = 1.f / sqrtf(v + 1e-5f);
                o4.x = (t0 - m) * inv * gsm[co0 + 0] + lbsm[co0 + 0];
                o4.y = (t1 - m) * inv * gsm[co0 + 1] + lbsm[co0 + 1];
                o4.z = (t2 - m) * inv * gsm[co0 + 2] + lbsm[co0 + 2];
                o4.w = (t3 - m) * inv * gsm[co0 + 3] + lbsm[co0 + 3];
            } else {
                o4.x = t0; o4.y = t1; o4.z = t2; o4.w = t3;
            }
            *(float4*)(outb + (size_t)(p0 + p) * ND + co0) = o4;
        }
    }
}

extern "C" void kernel_launch(void* const* d_in, const int* in_sizes, int n_in,
                              void* d_out, int out_size) {
    const float* x   = (const float*)d_in[0];
    const float* tw3 = (const float*)d_in[1];
    const float* tb3 = (const float*)d_in[2];
    const float* tw5 = (const float*)d_in[3];
    const float* tb5 = (const float*)d_in[4];
    const float* tw7 = (const float*)d_in[5];
    const float* tb7 = (const float*)d_in[6];
    const float* tw9 = (const float*)d_in[7];
    const float* tb9 = (const float*)d_in[8];
    const float* cw1 = (const float*)d_in[9];
    const float* cb1 = (const float*)d_in[10];
    const float* cw2 = (const float*)d_in[11];
    const float* cb2 = (const float*)d_in[12];
    const float* cw3 = (const float*)d_in[13];
    const float* cb3 = (const float*)d_in[14];
    const float* lg1 = (const float*)d_in[15];
    const float* lb1 = (const float*)d_in[16];
    const float* lg2 = (const float*)d_in[17];
    const float* lb2 = (const float*)d_in[18];
    (void)in_sizes; (void)n_in; (void)out_size;

    void *wt_p, *emb_p, *h1_p, *h2_p;
    cudaGetSymbolAddress(&wt_p,  g_wt);
    cudaGetSymbolAddress(&emb_p, g_emb);
    cudaGetSymbolAddress(&h1_p,  g_h1);
    cudaGetSymbolAddress(&h2_p,  g_h2);
    float* emb = (float*)emb_p;
    float* h1  = (float*)h1_p;
    float* h2  = (float*)h2_p;
    float* wtb = (float*)wt_p;

    const int smemsz = (8840 + 16384 + 192) * 4;   // 101,664 B -> 2 CTAs/SM
    cudaFuncSetAttribute((const void*)stage_kernel<true>,
                         cudaFuncAttributeMaxDynamicSharedMemorySize, smemsz);
    cudaFuncSetAttribute((const void*)stage_kernel<false>,
                         cudaFuncAttributeMaxDynamicSharedMemorySize, smemsz);

    pe_kernel<<<(NL0 * 32 + 255) / 256, 256>>>();
    wt_kernel<<<(3 * 64 * 64 * 4 + 255) / 256, 256>>>(cw1, cw2, cw3);

    dim3 eg(NL0 / 256, NB);
    emb_kernel<<<eg, 256>>>(x, tw3, tb3, tw5, tb5, tw7, tb7, tw9, tb9);

    stage_kernel<true ><<<296, 256, smemsz>>>(emb, h1, wtb + 0 * 128 * 128, cb1, lg1, lb1,
                                              NL0, NL1, NB * (NL1 / 64));
    stage_kernel<true ><<<296, 256, smemsz>>>(h1, h2, wtb + 1 * 128 * 128, cb2, lg2, lb2,
                                              NL1, NL2, NB * (NL2 / 64));
    stage_kernel<false><<<296, 256, smemsz>>>(h2, (float*)d_out, wtb + 2 * 128 * 128, cb3,
                                              nullptr, nullptr, NL2, NL3, NB * (NL3 / 64));
}